// round 3
// baseline (speedup 1.0000x reference)
#include <cuda_runtime.h>

#define HH 4096
#define WW 4096

__global__ __launch_bounds__(256) void nms_kernel(
    const float* __restrict__ img,
    const float* __restrict__ theta,
    float* __restrict__ out)
{
    int idx  = blockIdx.x * blockDim.x + threadIdx.x;   // quad index
    int lane = threadIdx.x & 31;
    int h  = idx >> 10;            // row (1024 quads per row; warps never straddle rows)
    int w0 = (idx & 1023) << 2;    // quad start column
    long base = (long)h * WW + w0;

    if (h == 0 || h == HH - 1) {
        *reinterpret_cast<float4*>(out + base) = make_float4(0.f, 0.f, 0.f, 0.f);
        return;
    }

    // ---- 4 vector loads (16 B each) ----
    const float4 t4 = __ldg(reinterpret_cast<const float4*>(theta + base));
    const float4 c4 = __ldg(reinterpret_cast<const float4*>(img + base));
    const float4 u4 = __ldg(reinterpret_cast<const float4*>(img + base - WW));
    const float4 d4 = __ldg(reinterpret_cast<const float4*>(img + base + WW));

    // ---- halo via warp shuffle: neighbor columns live in adjacent lanes ----
    float lftc = __shfl_up_sync(0xffffffffu, c4.w, 1);
    float lftu = __shfl_up_sync(0xffffffffu, u4.w, 1);
    float lftd = __shfl_up_sync(0xffffffffu, d4.w, 1);
    float rgtc = __shfl_down_sync(0xffffffffu, c4.x, 1);
    float rgtu = __shfl_down_sync(0xffffffffu, u4.x, 1);
    float rgtd = __shfl_down_sync(0xffffffffu, d4.x, 1);

    // warp-edge lanes fetch their halo from memory (predicated: 1 wavefront each).
    // Clamped corner addresses are never used (those pixels are border-zeroed).
    if (lane == 0) {
        long uli = base - WW - 1; if (uli < 0) uli = 0;
        lftc = __ldg(img + base - 1);
        lftu = __ldg(img + uli);
        lftd = __ldg(img + base + WW - 1);
    }
    if (lane == 31) {
        long dri = base + WW + 4; if (dri >= (long)HH * WW) dri = (long)HH * WW - 1;
        rgtc = __ldg(img + base + 4);
        rgtu = __ldg(img + base - WW + 4);
        rgtd = __ldg(img + dri);
    }

    // column j of these arrays = image column (w0 - 1 + j)
    float row[6] = { lftc, c4.x, c4.y, c4.z, c4.w, rgtc };
    float uu [6] = { lftu, u4.x, u4.y, u4.z, u4.w, rgtu };
    float dn [6] = { lftd, d4.x, d4.y, d4.z, d4.w, rgtd };
    float th [4] = { t4.x, t4.y, t4.z, t4.w };
    float o[4];

    const float RCP45 = 1.0f / 45.0f;   // RN(1/45)

    #pragma unroll
    for (int i = 0; i < 4; i++) {
        // deg = theta * f32(180/pi); single +180 if negative (matches reference)
        float deg = __fmul_rn(th[i], 57.29577951308232f);
        if (deg < 0.f) deg = __fadd_rn(deg, 180.f);

        // correctly-rounded deg/45 (Markstein mul+2fma, bit-exact vs RN divide)
        float q0 = __fmul_rn(deg, RCP45);
        float rr = __fmaf_rn(-45.f, q0, deg);
        float qf = __fmaf_rn(rr, RCP45, q0);
        int   k  = __float2int_rn(qf);      // F2I round-half-even == jnp.round

        // k: 0 or 4 -> 0/180deg; 1 -> 45; 2 -> 90; else -> 135 branch
        float a, b;
        if (k == 0 || k == 4) { a = row[i + 2]; b = row[i];     }
        else if (k == 1)      { a = dn [i + 2]; b = uu[i];      }
        else if (k == 2)      { a = dn [i + 1]; b = uu[i + 1];  }
        else                  { a = dn [i];     b = uu[i + 2];  }

        float cc = row[i + 1];
        o[i] = (cc >= fmaxf(a, b)) ? cc : 0.f;
    }

    // left / right image borders
    if (w0 == 0)       o[0] = 0.f;
    if (w0 == WW - 4)  o[3] = 0.f;

    *reinterpret_cast<float4*>(out + base) = make_float4(o[0], o[1], o[2], o[3]);
}

extern "C" void kernel_launch(void* const* d_in, const int* in_sizes, int n_in,
                              void* d_out, int out_size)
{
    const float* img   = (const float*)d_in[0];
    const float* theta = (const float*)d_in[1];
    float*       out   = (float*)d_out;

    const int n_quads = HH * (WW / 4);     // 4,194,304 threads
    const int block   = 256;
    const int grid    = n_quads / block;   // 16384
    nms_kernel<<<grid, block>>>(img, theta, out);
}

// round 4
// speedup vs baseline: 1.3119x; 1.3119x over previous
#include <cuda_runtime.h>

#define HH 4096
#define WW 4096
#define NPIX (HH * WW)

__global__ void __launch_bounds__(256, 7) nms_kernel(
    const float* __restrict__ img,
    const float* __restrict__ theta,
    float* __restrict__ out)
{
    unsigned idx = blockIdx.x * 256u + threadIdx.x;   // quad index
    unsigned h   = idx >> 10;            // row
    unsigned w0  = (idx & 1023u) << 2;   // quad start column
    unsigned base = (h << 12) + w0;      // 32-bit: max 16.7M

    if (h == 0 || h == HH - 1) {
        *reinterpret_cast<float4*>(out + base) = make_float4(0.f, 0.f, 0.f, 0.f);
        return;
    }

    const float* pc = img + base;   // single 64-bit base; all img loads at immediate offsets

    // ---- 10 independent loads, front-batched (MLP=10) ----
    const float4 t4 = __ldg(reinterpret_cast<const float4*>(theta + base));
    const float4 c4 = __ldg(reinterpret_cast<const float4*>(pc));
    const float4 u4 = __ldg(reinterpret_cast<const float4*>(pc - WW));
    const float4 d4 = __ldg(reinterpret_cast<const float4*>(pc + WW));

    // corner clamps only bind for (h==1,w0==0) / (h==HH-2,w0==WW-4); clamped
    // values are never used because those output pixels are border-zeroed.
    int uli = (int)base - WW - 1; if (uli < 0) uli = 0;
    int dri = (int)base + WW + 4; if (dri >= NPIX) dri = NPIX - 1;

    const float lft = __ldg(pc - 1);
    const float rgt = __ldg(pc + 4);
    const float ul  = __ldg(img + uli);
    const float ur  = __ldg(pc - WW + 4);
    const float dl  = __ldg(pc + WW - 1);
    const float dr  = __ldg(img + dri);

    // column j of these arrays = image column (w0 - 1 + j)
    float row[6] = { lft, c4.x, c4.y, c4.z, c4.w, rgt };
    float uu [6] = { ul,  u4.x, u4.y, u4.z, u4.w, ur  };
    float dn [6] = { dl,  d4.x, d4.y, d4.z, d4.w, dr  };
    float th [4] = { t4.x, t4.y, t4.z, t4.w };
    float o[4];

    const float RCP45 = 1.0f / 45.0f;   // RN(1/45)

    #pragma unroll
    for (int i = 0; i < 4; i++) {
        // deg = theta * f32(180/pi); single +180 if negative (matches reference)
        float deg = __fmul_rn(th[i], 57.29577951308232f);
        if (deg < 0.f) deg = __fadd_rn(deg, 180.f);

        // correctly-rounded deg/45 (Markstein mul+2fma, bit-exact vs RN divide)
        float q0 = __fmul_rn(deg, RCP45);
        float rr = __fmaf_rn(-45.f, q0, deg);
        float qf = __fmaf_rn(rr, RCP45, q0);
        int   k  = __float2int_rn(qf);      // F2I.RNI = round-half-even = jnp.round

        // k: 0 or 4 -> 0/180 deg; 1 -> 45; 2 -> 90; anything else -> 135
        float a, b;
        if (k == 0 || k == 4) { a = row[i + 2]; b = row[i];     }
        else if (k == 1)      { a = dn [i + 2]; b = uu[i];      }
        else if (k == 2)      { a = dn [i + 1]; b = uu[i + 1];  }
        else                  { a = dn [i];     b = uu[i + 2];  }

        float cc = row[i + 1];
        o[i] = (cc >= fmaxf(a, b)) ? cc : 0.f;
    }

    // left / right image borders
    if (w0 == 0)       o[0] = 0.f;
    if (w0 == WW - 4)  o[3] = 0.f;

    *reinterpret_cast<float4*>(out + base) = make_float4(o[0], o[1], o[2], o[3]);
}

extern "C" void kernel_launch(void* const* d_in, const int* in_sizes, int n_in,
                              void* d_out, int out_size)
{
    const float* img   = (const float*)d_in[0];
    const float* theta = (const float*)d_in[1];
    float*       out   = (float*)d_out;

    const int n_quads = HH * (WW / 4);     // 4,194,304 threads
    const int block   = 256;
    const int grid    = n_quads / block;   // 16384
    nms_kernel<<<grid, block>>>(img, theta, out);
}